// round 1
// baseline (speedup 1.0000x reference)
#include <cuda_runtime.h>
#include <cuda_bf16.h>
#include <math.h>

#define N_NODES 8192
#define D_FEAT  256
#define ALPHA   0.2f
#define NEG_INF -9e15f

// ---------------- scratch (no allocs allowed) ----------------
__device__ float g_Wh[N_NODES * D_FEAT];   // Wh of current layer
__device__ float g_h [N_NODES * D_FEAT];   // layer-1 output
__device__ float g_ssrc[N_NODES];
__device__ float g_sdst[N_NODES];

// ---------------- GEMM: C[N,D] = A[N,D] @ W[D,D] ----------------
// block tile 64x64, 256 threads, 4x4 micro-tile, BK=16
__global__ void gemm_kernel(const float* __restrict__ A,
                            const float* __restrict__ W,
                            float* __restrict__ C) {
    __shared__ float As[16][65];   // [k][m]
    __shared__ float Bs[16][64];   // [k][n] (unpadded: float4 reads)
    const int bm = blockIdx.y * 64;
    const int bn = blockIdx.x * 64;
    const int tid = threadIdx.x;
    const int tx = tid & 15;       // 16 col groups
    const int ty = tid >> 4;       // 16 row groups

    float acc[4][4];
#pragma unroll
    for (int r = 0; r < 4; r++)
#pragma unroll
        for (int c = 0; c < 4; c++) acc[r][c] = 0.f;

    for (int k0 = 0; k0 < D_FEAT; k0 += 16) {
#pragma unroll
        for (int i = tid; i < 64 * 16; i += 256) {
            int m = i >> 4, k = i & 15;
            As[k][m] = A[(size_t)(bm + m) * D_FEAT + k0 + k];
        }
#pragma unroll
        for (int i = tid; i < 16 * 64; i += 256) {
            int k = i >> 6, n = i & 63;
            Bs[k][n] = W[(size_t)(k0 + k) * D_FEAT + bn + n];
        }
        __syncthreads();
#pragma unroll
        for (int k = 0; k < 16; k++) {
            float a[4];
            float4 b = *(const float4*)&Bs[k][tx * 4];
#pragma unroll
            for (int r = 0; r < 4; r++) a[r] = As[k][ty * 4 + r];
#pragma unroll
            for (int r = 0; r < 4; r++) {
                acc[r][0] += a[r] * b.x;
                acc[r][1] += a[r] * b.y;
                acc[r][2] += a[r] * b.z;
                acc[r][3] += a[r] * b.w;
            }
        }
        __syncthreads();
    }
#pragma unroll
    for (int r = 0; r < 4; r++) {
        float4 v = make_float4(acc[r][0], acc[r][1], acc[r][2], acc[r][3]);
        *(float4*)&C[(size_t)(bm + ty * 4 + r) * D_FEAT + bn + tx * 4] = v;
    }
}

// ---------------- projections: s_src[i] = Wh[i,:]·a_src, s_dst likewise ----------------
__global__ void proj_kernel(const float* __restrict__ Wh,
                            const float* __restrict__ a_src,
                            const float* __restrict__ a_dst,
                            float* __restrict__ ssrc,
                            float* __restrict__ sdst) {
    const int warp = threadIdx.x >> 5;
    const int lane = threadIdx.x & 31;
    const int row  = blockIdx.x * 8 + warp;
    if (row >= N_NODES) return;
    const float4* wr = (const float4*)(Wh + (size_t)row * D_FEAT);
    const float4* as = (const float4*)a_src;
    const float4* ad = (const float4*)a_dst;
    float s1 = 0.f, s2 = 0.f;
#pragma unroll
    for (int k = 0; k < 2; k++) {
        int idx = lane + 32 * k;
        float4 w = wr[idx];
        float4 u = as[idx];
        float4 v = ad[idx];
        s1 += w.x * u.x + w.y * u.y + w.z * u.z + w.w * u.w;
        s2 += w.x * v.x + w.y * v.y + w.z * v.z + w.w * v.w;
    }
#pragma unroll
    for (int o = 16; o > 0; o >>= 1) {
        s1 += __shfl_xor_sync(0xFFFFFFFFu, s1, o);
        s2 += __shfl_xor_sync(0xFFFFFFFFu, s2, o);
    }
    if (lane == 0) { ssrc[row] = s1; sdst[row] = s2; }
}

// ---------------- fused flash-style GAT aggregation ----------------
// out[i,:] = relu( softmax_j( mask(leakyrelu(s_src[i]+s_dst[j])) ) @ Wh )
// block: 64 rows, 256 threads; column tiles of 32; online softmax
#define BM 64
#define BN 32

__global__ __launch_bounds__(256, 1)
void agg_kernel(const int* __restrict__ adj,
                const float* __restrict__ Wh,
                const float* __restrict__ ssrc,
                const float* __restrict__ sdst,
                float* __restrict__ out) {
    __shared__ float Whs[BN][D_FEAT];     // 32 KB
    __shared__ float P[BM][BN + 1];       // padded: phase-B column reads
    __shared__ float s_src_s[BM];
    __shared__ float s_m[BM], s_l[BM], s_scale[BM];

    const int i0  = blockIdx.x * BM;
    const int tid = threadIdx.x;
    const int tx  = tid & 15;   // 16 col groups of 16
    const int ty  = tid >> 4;   // 16 row groups of 4

    float acc[4][16];
#pragma unroll
    for (int r = 0; r < 4; r++)
#pragma unroll
        for (int c = 0; c < 16; c++) acc[r][c] = 0.f;

    if (tid < BM) {
        s_src_s[tid] = ssrc[i0 + tid];
        s_m[tid] = -3.0e38f;
        s_l[tid] = 0.f;
    }
    __syncthreads();

    const float4* WhV = (const float4*)Wh;

    for (int j0 = 0; j0 < N_NODES; j0 += BN) {
        // ---- Phase A: load Wh tile + compute masked leaky-relu scores ----
#pragma unroll
        for (int i = tid; i < BN * (D_FEAT / 4); i += 256) {
            int r = i >> 6, c = i & 63;
            ((float4*)Whs[r])[c] = WhV[(size_t)(j0 + r) * (D_FEAT / 4) + c];
        }
#pragma unroll
        for (int i = tid; i < BM * BN; i += 256) {
            int r = i >> 5, c = i & 31;
            int a = adj[(size_t)(i0 + r) * N_NODES + j0 + c];
            float e = s_src_s[r] + __ldg(&sdst[j0 + c]);
            e = (e > 0.f) ? e : ALPHA * e;
            P[r][c] = a ? e : NEG_INF;
        }
        __syncthreads();

        // ---- Phase B: per-row online softmax over this tile ----
        if (tid < BM) {
            const int r = tid;
            float m_old = s_m[r];
            float mx = m_old;
#pragma unroll
            for (int j = 0; j < BN; j++) mx = fmaxf(mx, P[r][j]);
            const float m_new = mx;
            const float scale = __expf(m_old - m_new);
            float sum = 0.f;
#pragma unroll
            for (int j = 0; j < BN; j++) {
                float p = __expf(P[r][j] - m_new);
                P[r][j] = p;
                sum += p;
            }
            s_l[r] = s_l[r] * scale + sum;
            s_m[r] = m_new;
            s_scale[r] = scale;
        }
        __syncthreads();

        // ---- Phase C: rescale accumulators + acc += P @ Wh_tile ----
#pragma unroll
        for (int r = 0; r < 4; r++) {
            float sc = s_scale[ty * 4 + r];
#pragma unroll
            for (int c = 0; c < 16; c++) acc[r][c] *= sc;
        }
#pragma unroll 4
        for (int j = 0; j < BN; j++) {
            float p[4];
#pragma unroll
            for (int r = 0; r < 4; r++) p[r] = P[ty * 4 + r][j];
#pragma unroll
            for (int q = 0; q < 4; q++) {
                float4 w = *(const float4*)&Whs[j][tx * 16 + q * 4];
#pragma unroll
                for (int r = 0; r < 4; r++) {
                    acc[r][q * 4 + 0] += p[r] * w.x;
                    acc[r][q * 4 + 1] += p[r] * w.y;
                    acc[r][q * 4 + 2] += p[r] * w.z;
                    acc[r][q * 4 + 3] += p[r] * w.w;
                }
            }
        }
        __syncthreads();
    }

    // ---- epilogue: divide by l, relu, store ----
#pragma unroll
    for (int r = 0; r < 4; r++) {
        const int row = i0 + ty * 4 + r;
        const float inv = 1.0f / s_l[ty * 4 + r];
#pragma unroll
        for (int q = 0; q < 4; q++) {
            float4 v;
            v.x = fmaxf(acc[r][q * 4 + 0] * inv, 0.f);
            v.y = fmaxf(acc[r][q * 4 + 1] * inv, 0.f);
            v.z = fmaxf(acc[r][q * 4 + 2] * inv, 0.f);
            v.w = fmaxf(acc[r][q * 4 + 3] * inv, 0.f);
            *(float4*)&out[(size_t)row * D_FEAT + tx * 16 + q * 4] = v;
        }
    }
}

// ---------------- launch ----------------
extern "C" void kernel_launch(void* const* d_in, const int* in_sizes, int n_in,
                              void* d_out, int out_size) {
    const float* x     = (const float*)d_in[0];
    const int*   adj   = (const int*)  d_in[1];
    const float* W1    = (const float*)d_in[2];
    const float* a1src = (const float*)d_in[3];
    const float* a1dst = (const float*)d_in[4];
    const float* W2    = (const float*)d_in[5];
    const float* a2src = (const float*)d_in[6];
    const float* a2dst = (const float*)d_in[7];
    float* out = (float*)d_out;

    float *Wh, *h1, *ss, *sd;
    cudaGetSymbolAddress((void**)&Wh, g_Wh);
    cudaGetSymbolAddress((void**)&h1, g_h);
    cudaGetSymbolAddress((void**)&ss, g_ssrc);
    cudaGetSymbolAddress((void**)&sd, g_sdst);

    dim3 ggrid(D_FEAT / 64, N_NODES / 64);

    // layer 1
    gemm_kernel<<<ggrid, 256>>>(x, W1, Wh);
    proj_kernel<<<N_NODES / 8, 256>>>(Wh, a1src, a1dst, ss, sd);
    agg_kernel<<<N_NODES / BM, 256>>>(adj, Wh, ss, sd, h1);

    // layer 2
    gemm_kernel<<<ggrid, 256>>>(h1, W2, Wh);
    proj_kernel<<<N_NODES / 8, 256>>>(Wh, a2src, a2dst, ss, sd);
    agg_kernel<<<N_NODES / BM, 256>>>(adj, Wh, ss, sd, out);
}

// round 2
// speedup vs baseline: 3.0281x; 3.0281x over previous
#include <cuda_runtime.h>
#include <mma.h>
#include <math.h>

using namespace nvcuda;

#define N_NODES 8192
#define D_FEAT  256
#define ALPHA   0.2f

// ---------------- scratch (no allocs allowed) ----------------
__device__ float g_Wh[N_NODES * D_FEAT];
__device__ float g_h [N_NODES * D_FEAT];
__device__ float g_ssrc[N_NODES];
__device__ float g_sdst[N_NODES];
__device__ float g_F1[N_NODES];
__device__ float g_F2[N_NODES];
__device__ float g_A1[N_NODES];
__device__ float g_A2[N_NODES];

// ---------------- GEMM: C[N,D] = A[N,D] @ W[D,D] (fp32, unchanged) ----------------
__global__ void gemm_kernel(const float* __restrict__ A,
                            const float* __restrict__ W,
                            float* __restrict__ C) {
    __shared__ float As[16][65];
    __shared__ float Bs[16][64];
    const int bm = blockIdx.y * 64;
    const int bn = blockIdx.x * 64;
    const int tid = threadIdx.x;
    const int tx = tid & 15;
    const int ty = tid >> 4;

    float acc[4][4];
#pragma unroll
    for (int r = 0; r < 4; r++)
#pragma unroll
        for (int c = 0; c < 4; c++) acc[r][c] = 0.f;

    for (int k0 = 0; k0 < D_FEAT; k0 += 16) {
#pragma unroll
        for (int i = tid; i < 64 * 16; i += 256) {
            int m = i >> 4, k = i & 15;
            As[k][m] = A[(size_t)(bm + m) * D_FEAT + k0 + k];
        }
#pragma unroll
        for (int i = tid; i < 16 * 64; i += 256) {
            int k = i >> 6, n = i & 63;
            Bs[k][n] = W[(size_t)(k0 + k) * D_FEAT + bn + n];
        }
        __syncthreads();
#pragma unroll
        for (int k = 0; k < 16; k++) {
            float a[4];
            float4 b = *(const float4*)&Bs[k][tx * 4];
#pragma unroll
            for (int r = 0; r < 4; r++) a[r] = As[k][ty * 4 + r];
#pragma unroll
            for (int r = 0; r < 4; r++) {
                acc[r][0] += a[r] * b.x;
                acc[r][1] += a[r] * b.y;
                acc[r][2] += a[r] * b.z;
                acc[r][3] += a[r] * b.w;
            }
        }
        __syncthreads();
    }
#pragma unroll
    for (int r = 0; r < 4; r++) {
        float4 v = make_float4(acc[r][0], acc[r][1], acc[r][2], acc[r][3]);
        *(float4*)&C[(size_t)(bm + ty * 4 + r) * D_FEAT + bn + tx * 4] = v;
    }
}

// ---------------- projections: s_src / s_dst ----------------
__global__ void proj_kernel(const float* __restrict__ Wh,
                            const float* __restrict__ a_src,
                            const float* __restrict__ a_dst,
                            float* __restrict__ ssrc,
                            float* __restrict__ sdst) {
    const int warp = threadIdx.x >> 5;
    const int lane = threadIdx.x & 31;
    const int row  = blockIdx.x * 8 + warp;
    if (row >= N_NODES) return;
    const float4* wr = (const float4*)(Wh + (size_t)row * D_FEAT);
    const float4* as = (const float4*)a_src;
    const float4* ad = (const float4*)a_dst;
    float s1 = 0.f, s2 = 0.f;
#pragma unroll
    for (int k = 0; k < 2; k++) {
        int idx = lane + 32 * k;
        float4 w = wr[idx];
        float4 u = as[idx];
        float4 v = ad[idx];
        s1 += w.x * u.x + w.y * u.y + w.z * u.z + w.w * u.w;
        s2 += w.x * v.x + w.y * v.y + w.z * v.z + w.w * v.w;
    }
#pragma unroll
    for (int o = 16; o > 0; o >>= 1) {
        s1 += __shfl_xor_sync(0xFFFFFFFFu, s1, o);
        s2 += __shfl_xor_sync(0xFFFFFFFFu, s2, o);
    }
    if (lane == 0) { ssrc[row] = s1; sdst[row] = s2; }
}

// ---------------- column factors: F1 = exp(sdst), F2 = exp(alpha*sdst) ----------------
__global__ void factor_kernel(const float* __restrict__ sdst,
                              float* __restrict__ F1, float* __restrict__ F2) {
    int j = blockIdx.x * 256 + threadIdx.x;
    float s = sdst[j];
    F1[j] = expf(s);
    F2[j] = expf(ALPHA * s);
}

// ---------------- per-row softmax stats -> normalized row coefficients ----------------
// S1 = sum_{adj, s_i+s_j>0} F1_j ; S2 = sum_{adj, s_i+s_j<=0} F2_j
// A1 = 1/(S1 + g*S2), A2 = g*A1, g = exp((alpha-1)*s_i)
__global__ void stats_kernel(const int* __restrict__ adj,
                             const float* __restrict__ ssrc,
                             const float* __restrict__ sdst,
                             const float* __restrict__ F1,
                             const float* __restrict__ F2,
                             float* __restrict__ A1,
                             float* __restrict__ A2) {
    const int warp = threadIdx.x >> 5;
    const int lane = threadIdx.x & 31;
    const int row  = blockIdx.x * 8 + warp;
    const float si = ssrc[row];
    const float th = -si;
    const int4*   av  = (const int4*)(adj + (size_t)row * N_NODES);
    const float4* f1v = (const float4*)F1;
    const float4* f2v = (const float4*)F2;
    const float4* sdv = (const float4*)sdst;
    float S1 = 0.f, S2 = 0.f;
    for (int c = lane; c < N_NODES / 4; c += 32) {
        int4   a  = av[c];
        float4 f1 = __ldg(f1v + c);
        float4 f2 = __ldg(f2v + c);
        float4 sd = __ldg(sdv + c);
        if (a.x) { if (sd.x > th) S1 += f1.x; else S2 += f2.x; }
        if (a.y) { if (sd.y > th) S1 += f1.y; else S2 += f2.y; }
        if (a.z) { if (sd.z > th) S1 += f1.z; else S2 += f2.z; }
        if (a.w) { if (sd.w > th) S1 += f1.w; else S2 += f2.w; }
    }
#pragma unroll
    for (int o = 16; o > 0; o >>= 1) {
        S1 += __shfl_xor_sync(0xFFFFFFFFu, S1, o);
        S2 += __shfl_xor_sync(0xFFFFFFFFu, S2, o);
    }
    if (lane == 0) {
        float g   = expf((ALPHA - 1.f) * si);
        float inv = 1.f / (S1 + g * S2);
        A1[row] = inv;
        A2[row] = g * inv;
    }
}

// ---------------- fused aggregation: out = relu(P @ Wh), P built on the fly ----------------
// tf32 wmma m16n16k8; BM=64 rows/block, col tile BN=32, 8 warps.
#define BM 64
#define BN 32
#define WHS_LD 264   // 256 + 8 pad
#define PS_LD  36    // 32 + 4 pad

__global__ __launch_bounds__(256, 1)
void agg_kernel(const int* __restrict__ adj,
                const float* __restrict__ Wh,
                const float* __restrict__ ssrc,
                const float* __restrict__ sdst,
                const float* __restrict__ F1,
                const float* __restrict__ F2,
                const float* __restrict__ A1,
                const float* __restrict__ A2,
                float* __restrict__ out) {
    __shared__ float Whs[BN][WHS_LD];       // 33 KB
    __shared__ float Ps [BM][PS_LD];        // 9 KB
    __shared__ float A1s[BM], A2s[BM], THs[BM];

    const int i0   = blockIdx.x * BM;
    const int tid  = threadIdx.x;
    const int warp = tid >> 5;
    const int rg   = warp >> 1;   // 0..3 : 16-row group
    const int cg   = warp & 1;    // 0..1 : 128-col group

    if (tid < BM) {
        A1s[tid] = A1[i0 + tid];
        A2s[tid] = A2[i0 + tid];
        THs[tid] = -ssrc[i0 + tid];
    }

    wmma::fragment<wmma::accumulator, 16, 16, 8, float> acc[8];
#pragma unroll
    for (int f = 0; f < 8; f++) wmma::fill_fragment(acc[f], 0.f);

    __syncthreads();

    const int pr = tid >> 2;         // row 0..63 for P compute
    const int pq = tid & 3;          // col quad: 8 cols each

    for (int j0 = 0; j0 < N_NODES; j0 += BN) {
        // ---- load Wh tile [32 x 256] as tf32 ----
        const float4* wv = (const float4*)(Wh + (size_t)j0 * D_FEAT);
#pragma unroll
        for (int i = tid; i < BN * (D_FEAT / 4); i += 256) {
            int r = i >> 6, c = i & 63;
            float4 v = wv[(size_t)r * (D_FEAT / 4) + c];
            float* dst = &Whs[r][c * 4];
            dst[0] = wmma::__float_to_tf32(v.x);
            dst[1] = wmma::__float_to_tf32(v.y);
            dst[2] = wmma::__float_to_tf32(v.z);
            dst[3] = wmma::__float_to_tf32(v.w);
        }
        // ---- compute P tile [64 x 32]: no exp, pure select ----
        {
            const int jc = j0 + pq * 8;
            const int*  arow = adj + (size_t)(i0 + pr) * N_NODES + jc;
            int4   a0  = *(const int4*)(arow);
            int4   a1  = *(const int4*)(arow + 4);
            float4 f1a = *(const float4*)(F1 + jc);
            float4 f1b = *(const float4*)(F1 + jc + 4);
            float4 f2a = *(const float4*)(F2 + jc);
            float4 f2b = *(const float4*)(F2 + jc + 4);
            float4 sda = *(const float4*)(sdst + jc);
            float4 sdb = *(const float4*)(sdst + jc + 4);
            const float c1 = A1s[pr], c2 = A2s[pr], th = THs[pr];
            float* p = &Ps[pr][pq * 8];
            p[0] = wmma::__float_to_tf32(a0.x ? (sda.x > th ? c1 * f1a.x : c2 * f2a.x) : 0.f);
            p[1] = wmma::__float_to_tf32(a0.y ? (sda.y > th ? c1 * f1a.y : c2 * f2a.y) : 0.f);
            p[2] = wmma::__float_to_tf32(a0.z ? (sda.z > th ? c1 * f1a.z : c2 * f2a.z) : 0.f);
            p[3] = wmma::__float_to_tf32(a0.w ? (sda.w > th ? c1 * f1a.w : c2 * f2a.w) : 0.f);
            p[4] = wmma::__float_to_tf32(a1.x ? (sdb.x > th ? c1 * f1b.x : c2 * f2b.x) : 0.f);
            p[5] = wmma::__float_to_tf32(a1.y ? (sdb.y > th ? c1 * f1b.y : c2 * f2b.y) : 0.f);
            p[6] = wmma::__float_to_tf32(a1.z ? (sdb.z > th ? c1 * f1b.z : c2 * f2b.z) : 0.f);
            p[7] = wmma::__float_to_tf32(a1.w ? (sdb.w > th ? c1 * f1b.w : c2 * f2b.w) : 0.f);
        }
        __syncthreads();

        // ---- acc += P(64x32) @ WhTile(32x256) on tensor cores ----
#pragma unroll
        for (int kk = 0; kk < BN; kk += 8) {
            wmma::fragment<wmma::matrix_a, 16, 16, 8, wmma::precision::tf32, wmma::row_major> af;
            wmma::load_matrix_sync(af, &Ps[rg * 16][kk], PS_LD);
#pragma unroll
            for (int nf = 0; nf < 8; nf++) {
                wmma::fragment<wmma::matrix_b, 16, 16, 8, wmma::precision::tf32, wmma::row_major> bf;
                wmma::load_matrix_sync(bf, &Whs[kk][cg * 128 + nf * 16], WHS_LD);
                wmma::mma_sync(acc[nf], af, bf, acc[nf]);
            }
        }
        __syncthreads();
    }

    // ---- epilogue: relu + store (attn already normalized via A1/A2) ----
#pragma unroll
    for (int nf = 0; nf < 8; nf++) {
#pragma unroll
        for (int e = 0; e < acc[nf].num_elements; e++)
            acc[nf].x[e] = fmaxf(acc[nf].x[e], 0.f);
        wmma::store_matrix_sync(out + (size_t)(i0 + rg * 16) * D_FEAT + cg * 128 + nf * 16,
                                acc[nf], D_FEAT, wmma::mem_row_major);
    }
}

// ---------------- launch ----------------
extern "C" void kernel_launch(void* const* d_in, const int* in_sizes, int n_in,
                              void* d_out, int out_size) {
    const float* x     = (const float*)d_in[0];
    const int*   adj   = (const int*)  d_in[1];
    const float* W1    = (const float*)d_in[2];
    const float* a1src = (const float*)d_in[3];
    const float* a1dst = (const float*)d_in[4];
    const float* W2    = (const float*)d_in[5];
    const float* a2src = (const float*)d_in[6];
    const float* a2dst = (const float*)d_in[7];
    float* out = (float*)d_out;

    float *Wh, *h1, *ss, *sd, *F1, *F2, *A1, *A2;
    cudaGetSymbolAddress((void**)&Wh, g_Wh);
    cudaGetSymbolAddress((void**)&h1, g_h);
    cudaGetSymbolAddress((void**)&ss, g_ssrc);
    cudaGetSymbolAddress((void**)&sd, g_sdst);
    cudaGetSymbolAddress((void**)&F1, g_F1);
    cudaGetSymbolAddress((void**)&F2, g_F2);
    cudaGetSymbolAddress((void**)&A1, g_A1);
    cudaGetSymbolAddress((void**)&A2, g_A2);

    dim3 ggrid(D_FEAT / 64, N_NODES / 64);

    // ---- layer 1 ----
    gemm_kernel<<<ggrid, 256>>>(x, W1, Wh);
    proj_kernel<<<N_NODES / 8, 256>>>(Wh, a1src, a1dst, ss, sd);
    factor_kernel<<<N_NODES / 256, 256>>>(sd, F1, F2);
    stats_kernel<<<N_NODES / 8, 256>>>(adj, ss, sd, F1, F2, A1, A2);
    agg_kernel<<<N_NODES / BM, 256>>>(adj, Wh, ss, sd, F1, F2, A1, A2, h1);

    // ---- layer 2 ----
    gemm_kernel<<<ggrid, 256>>>(h1, W2, Wh);
    proj_kernel<<<N_NODES / 8, 256>>>(Wh, a2src, a2dst, ss, sd);
    factor_kernel<<<N_NODES / 256, 256>>>(sd, F1, F2);
    stats_kernel<<<N_NODES / 8, 256>>>(adj, ss, sd, F1, F2, A1, A2);
    agg_kernel<<<N_NODES / BM, 256>>>(adj, Wh, ss, sd, F1, F2, A1, A2, out);
}

// round 3
// speedup vs baseline: 6.0708x; 2.0048x over previous
#include <cuda_runtime.h>
#include <cuda_fp16.h>
#include <mma.h>
#include <math.h>

using namespace nvcuda;

#define N_NODES 8192
#define D_FEAT  256
#define ALPHA   0.2f

// ---------------- scratch (no allocs allowed) ----------------
__device__ float g_Wh[N_NODES * D_FEAT];
__device__ float g_h [N_NODES * D_FEAT];
__device__ float g_ssrc[N_NODES];
__device__ float g_sdst[N_NODES];
__device__ float g_F1[N_NODES];
__device__ float g_F2[N_NODES];
__device__ float g_G [N_NODES];
__device__ float g_L [N_NODES];

// ---------------- GEMM: C[N,D] = A[N,D] @ W[D,D] (fp32) ----------------
__global__ void gemm_kernel(const float* __restrict__ A,
                            const float* __restrict__ W,
                            float* __restrict__ C) {
    __shared__ float As[16][65];
    __shared__ float Bs[16][64];
    const int bm = blockIdx.y * 64;
    const int bn = blockIdx.x * 64;
    const int tid = threadIdx.x;
    const int tx = tid & 15;
    const int ty = tid >> 4;

    float acc[4][4];
#pragma unroll
    for (int r = 0; r < 4; r++)
#pragma unroll
        for (int c = 0; c < 4; c++) acc[r][c] = 0.f;

    for (int k0 = 0; k0 < D_FEAT; k0 += 16) {
#pragma unroll
        for (int i = tid; i < 64 * 16; i += 256) {
            int m = i >> 4, k = i & 15;
            As[k][m] = A[(size_t)(bm + m) * D_FEAT + k0 + k];
        }
#pragma unroll
        for (int i = tid; i < 16 * 64; i += 256) {
            int k = i >> 6, n = i & 63;
            Bs[k][n] = W[(size_t)(k0 + k) * D_FEAT + bn + n];
        }
        __syncthreads();
#pragma unroll
        for (int k = 0; k < 16; k++) {
            float a[4];
            float4 b = *(const float4*)&Bs[k][tx * 4];
#pragma unroll
            for (int r = 0; r < 4; r++) a[r] = As[k][ty * 4 + r];
#pragma unroll
            for (int r = 0; r < 4; r++) {
                acc[r][0] += a[r] * b.x;
                acc[r][1] += a[r] * b.y;
                acc[r][2] += a[r] * b.z;
                acc[r][3] += a[r] * b.w;
            }
        }
        __syncthreads();
    }
#pragma unroll
    for (int r = 0; r < 4; r++) {
        float4 v = make_float4(acc[r][0], acc[r][1], acc[r][2], acc[r][3]);
        *(float4*)&C[(size_t)(bm + ty * 4 + r) * D_FEAT + bn + tx * 4] = v;
    }
}

// ---------------- projections: s_src / s_dst ----------------
__global__ void proj_kernel(const float* __restrict__ Wh,
                            const float* __restrict__ a_src,
                            const float* __restrict__ a_dst,
                            float* __restrict__ ssrc,
                            float* __restrict__ sdst) {
    const int warp = threadIdx.x >> 5;
    const int lane = threadIdx.x & 31;
    const int row  = blockIdx.x * 8 + warp;
    if (row >= N_NODES) return;
    const float4* wr = (const float4*)(Wh + (size_t)row * D_FEAT);
    const float4* as = (const float4*)a_src;
    const float4* ad = (const float4*)a_dst;
    float s1 = 0.f, s2 = 0.f;
#pragma unroll
    for (int k = 0; k < 2; k++) {
        int idx = lane + 32 * k;
        float4 w = wr[idx];
        float4 u = as[idx];
        float4 v = ad[idx];
        s1 += w.x * u.x + w.y * u.y + w.z * u.z + w.w * u.w;
        s2 += w.x * v.x + w.y * v.y + w.z * v.z + w.w * v.w;
    }
#pragma unroll
    for (int o = 16; o > 0; o >>= 1) {
        s1 += __shfl_xor_sync(0xFFFFFFFFu, s1, o);
        s2 += __shfl_xor_sync(0xFFFFFFFFu, s2, o);
    }
    if (lane == 0) { ssrc[row] = s1; sdst[row] = s2; }
}

// ---------------- factors: F1=exp(sdst), F2=exp(a*sdst), G=exp((a-1)*ssrc) ----------------
__global__ void factor_kernel(const float* __restrict__ ssrc,
                              const float* __restrict__ sdst,
                              float* __restrict__ F1, float* __restrict__ F2,
                              float* __restrict__ G) {
    int j = blockIdx.x * 256 + threadIdx.x;
    float sd = sdst[j];
    float ss = ssrc[j];
    F1[j] = expf(sd);
    F2[j] = expf(ALPHA * sd);
    G[j]  = expf((ALPHA - 1.f) * ss);
}

// ---------------- fused aggregation (fp16 tensor cores) ----------------
// accU = P' @ Wh  (unnormalized),  L_i = row sums of P'.
// P'_ij = adj ? (ssrc_i+sdst_j > 0 ? F1_j : G_i*F2_j) : 0
#define BM 64
#define BN 64
#define WHS_LD 272   // halves: 256 + 16 pad
#define PS_LD  72    // halves: 64 + 8 pad

__global__ __launch_bounds__(256, 1)
void agg_kernel(const int* __restrict__ adj,
                const float* __restrict__ Wh,
                const float* __restrict__ ssrc,
                const float* __restrict__ sdst,
                const float* __restrict__ F1,
                const float* __restrict__ F2,
                const float* __restrict__ G,
                float* __restrict__ accU,
                float* __restrict__ Lout) {
    __shared__ half Whs[BN][WHS_LD];    // 34.8 KB
    __shared__ half Ps [BM][PS_LD];     // 9.2 KB
    __shared__ float Gs[BM], THs[BM];

    const int i0   = blockIdx.x * BM;
    const int tid  = threadIdx.x;
    const int warp = tid >> 5;
    const int rg   = warp >> 1;   // 0..3 : 16-row group
    const int cg   = warp & 1;    // 0..1 : 128-col group

    if (tid < BM) {
        Gs[tid]  = G[i0 + tid];
        THs[tid] = -ssrc[i0 + tid];
    }

    wmma::fragment<wmma::accumulator, 16, 16, 16, float> acc[8];
#pragma unroll
    for (int f = 0; f < 8; f++) wmma::fill_fragment(acc[f], 0.f);

    __syncthreads();

    const int pr = tid >> 2;   // row 0..63
    const int pq = tid & 3;    // 16-col quad
    float Lacc = 0.f;

    for (int j0 = 0; j0 < N_NODES; j0 += BN) {
        // ---- load Wh tile [64 x 256] fp32 -> fp16 smem ----
        const float4* wv = (const float4*)(Wh + (size_t)j0 * D_FEAT);
#pragma unroll
        for (int i = tid; i < BN * (D_FEAT / 4); i += 256) {
            int r = i >> 6, c = i & 63;
            float4 v = wv[(size_t)r * (D_FEAT / 4) + c];
            half2* dst = (half2*)&Whs[r][c * 4];
            dst[0] = __floats2half2_rn(v.x, v.y);
            dst[1] = __floats2half2_rn(v.z, v.w);
        }
        // ---- P tile [64 x 64], 16 cols per thread; accumulate row sums ----
        {
            const int jc = j0 + pq * 16;
            const int*   arow = adj + (size_t)(i0 + pr) * N_NODES + jc;
            const float  gi = Gs[pr], th = THs[pr];
            half2* pp = (half2*)&Ps[pr][pq * 16];
            float tsum = 0.f;
#pragma unroll
            for (int q = 0; q < 4; q++) {
                int4   a  = *(const int4*)(arow + q * 4);
                float4 f1 = *(const float4*)(F1 + jc + q * 4);
                float4 f2 = *(const float4*)(F2 + jc + q * 4);
                float4 sd = *(const float4*)(sdst + jc + q * 4);
                float p0 = a.x ? (sd.x > th ? f1.x : gi * f2.x) : 0.f;
                float p1 = a.y ? (sd.y > th ? f1.y : gi * f2.y) : 0.f;
                float p2 = a.z ? (sd.z > th ? f1.z : gi * f2.z) : 0.f;
                float p3 = a.w ? (sd.w > th ? f1.w : gi * f2.w) : 0.f;
                half2 h01 = __floats2half2_rn(p0, p1);
                half2 h23 = __floats2half2_rn(p2, p3);
                pp[q * 2 + 0] = h01;
                pp[q * 2 + 1] = h23;
                // sum the half-rounded values for numerator/denominator consistency
                float2 l01 = __half22float2(h01);
                float2 l23 = __half22float2(h23);
                tsum += (l01.x + l01.y) + (l23.x + l23.y);
            }
            Lacc += tsum;
        }
        __syncthreads();

        // ---- acc += P'(64x64) @ WhTile(64x256) ----
#pragma unroll
        for (int kk = 0; kk < BN; kk += 16) {
            wmma::fragment<wmma::matrix_a, 16, 16, 16, half, wmma::row_major> af;
            wmma::load_matrix_sync(af, &Ps[rg * 16][kk], PS_LD);
#pragma unroll
            for (int nf = 0; nf < 8; nf++) {
                wmma::fragment<wmma::matrix_b, 16, 16, 16, half, wmma::row_major> bf;
                wmma::load_matrix_sync(bf, &Whs[kk][cg * 128 + nf * 16], WHS_LD);
                wmma::mma_sync(acc[nf], af, bf, acc[nf]);
            }
        }
        __syncthreads();
    }

    // ---- row sums: reduce over the 4 quad threads (consecutive lanes) ----
    Lacc += __shfl_xor_sync(0xFFFFFFFFu, Lacc, 1);
    Lacc += __shfl_xor_sync(0xFFFFFFFFu, Lacc, 2);
    if (pq == 0) Lout[i0 + pr] = Lacc;

    // ---- store unnormalized accumulators ----
#pragma unroll
    for (int nf = 0; nf < 8; nf++) {
        wmma::store_matrix_sync(accU + (size_t)(i0 + rg * 16) * D_FEAT + cg * 128 + nf * 16,
                                acc[nf], D_FEAT, wmma::mem_row_major);
    }
}

// ---------------- normalize: out = relu(accU) / L  (in place) ----------------
__global__ void norm_kernel(float* __restrict__ buf, const float* __restrict__ L) {
    int idx = blockIdx.x * 256 + threadIdx.x;          // float4 index
    int row = idx >> 6;                                 // D/4 = 64
    float inv = 1.0f / __ldg(&L[row]);
    float4 v = ((float4*)buf)[idx];
    v.x = fmaxf(v.x, 0.f) * inv;
    v.y = fmaxf(v.y, 0.f) * inv;
    v.z = fmaxf(v.z, 0.f) * inv;
    v.w = fmaxf(v.w, 0.f) * inv;
    ((float4*)buf)[idx] = v;
}

// ---------------- launch ----------------
extern "C" void kernel_launch(void* const* d_in, const int* in_sizes, int n_in,
                              void* d_out, int out_size) {
    const float* x     = (const float*)d_in[0];
    const int*   adj   = (const int*)  d_in[1];
    const float* W1    = (const float*)d_in[2];
    const float* a1src = (const float*)d_in[3];
    const float* a1dst = (const float*)d_in[4];
    const float* W2    = (const float*)d_in[5];
    const float* a2src = (const float*)d_in[6];
    const float* a2dst = (const float*)d_in[7];
    float* out = (float*)d_out;

    float *Wh, *h1, *ss, *sd, *F1, *F2, *G, *L;
    cudaGetSymbolAddress((void**)&Wh, g_Wh);
    cudaGetSymbolAddress((void**)&h1, g_h);
    cudaGetSymbolAddress((void**)&ss, g_ssrc);
    cudaGetSymbolAddress((void**)&sd, g_sdst);
    cudaGetSymbolAddress((void**)&F1, g_F1);
    cudaGetSymbolAddress((void**)&F2, g_F2);
    cudaGetSymbolAddress((void**)&G,  g_G);
    cudaGetSymbolAddress((void**)&L,  g_L);

    dim3 ggrid(D_FEAT / 64, N_NODES / 64);
    const int nrm_blocks = (N_NODES * D_FEAT / 4) / 256;

    // ---- layer 1 ----
    gemm_kernel<<<ggrid, 256>>>(x, W1, Wh);
    proj_kernel<<<N_NODES / 8, 256>>>(Wh, a1src, a1dst, ss, sd);
    factor_kernel<<<N_NODES / 256, 256>>>(ss, sd, F1, F2, G);
    agg_kernel<<<N_NODES / BM, 256>>>(adj, Wh, ss, sd, F1, F2, G, h1, L);
    norm_kernel<<<nrm_blocks, 256>>>(h1, L);

    // ---- layer 2 ----
    gemm_kernel<<<ggrid, 256>>>(h1, W2, Wh);
    proj_kernel<<<N_NODES / 8, 256>>>(Wh, a2src, a2dst, ss, sd);
    factor_kernel<<<N_NODES / 256, 256>>>(ss, sd, F1, F2, G);
    agg_kernel<<<N_NODES / BM, 256>>>(adj, Wh, ss, sd, F1, F2, G, out, L);
    norm_kernel<<<nrm_blocks, 256>>>(out, L);
}

// round 5
// speedup vs baseline: 6.2172x; 1.0241x over previous
#include <cuda_runtime.h>
#include <cuda_fp16.h>
#include <mma.h>
#include <math.h>

using namespace nvcuda;

#define N_NODES 8192
#define D_FEAT  256
#define ALPHA   0.2f

#define BM 64
#define BN 64
#define NT (N_NODES / BN)      // 128 j-tiles
#define WHS_LD 272             // 256 + 16 pad (halves)
#define PS_LD  72              // 64 + 8 pad (halves)

// ---------------- scratch (no allocs allowed) ----------------
__device__ float g_Wh[N_NODES * D_FEAT];
__device__ float g_h [N_NODES * D_FEAT];
__device__ float g_ssrc[N_NODES];
__device__ float g_sdst[N_NODES];
__device__ float g_F1[N_NODES];
__device__ float g_F2[N_NODES];
__device__ float g_G [N_NODES];
__device__ float g_L [N_NODES];

// ---------------- GEMM: C[N,D] = A[N,D] @ W[D,D] (fp32) ----------------
__global__ void gemm_kernel(const float* __restrict__ A,
                            const float* __restrict__ W,
                            float* __restrict__ C) {
    __shared__ float As[16][65];
    __shared__ float Bs[16][64];
    const int bm = blockIdx.y * 64;
    const int bn = blockIdx.x * 64;
    const int tid = threadIdx.x;
    const int tx = tid & 15;
    const int ty = tid >> 4;

    float acc[4][4];
#pragma unroll
    for (int r = 0; r < 4; r++)
#pragma unroll
        for (int c = 0; c < 4; c++) acc[r][c] = 0.f;

    for (int k0 = 0; k0 < D_FEAT; k0 += 16) {
#pragma unroll
        for (int i = tid; i < 64 * 16; i += 256) {
            int m = i >> 4, k = i & 15;
            As[k][m] = A[(size_t)(bm + m) * D_FEAT + k0 + k];
        }
#pragma unroll
        for (int i = tid; i < 16 * 64; i += 256) {
            int k = i >> 6, n = i & 63;
            Bs[k][n] = W[(size_t)(k0 + k) * D_FEAT + bn + n];
        }
        __syncthreads();
#pragma unroll
        for (int k = 0; k < 16; k++) {
            float a[4];
            float4 b = *(const float4*)&Bs[k][tx * 4];
#pragma unroll
            for (int r = 0; r < 4; r++) a[r] = As[k][ty * 4 + r];
#pragma unroll
            for (int r = 0; r < 4; r++) {
                acc[r][0] += a[r] * b.x;
                acc[r][1] += a[r] * b.y;
                acc[r][2] += a[r] * b.z;
                acc[r][3] += a[r] * b.w;
            }
        }
        __syncthreads();
    }
#pragma unroll
    for (int r = 0; r < 4; r++) {
        float4 v = make_float4(acc[r][0], acc[r][1], acc[r][2], acc[r][3]);
        *(float4*)&C[(size_t)(bm + ty * 4 + r) * D_FEAT + bn + tx * 4] = v;
    }
}

// ---------------- projections ----------------
__global__ void proj_kernel(const float* __restrict__ Wh,
                            const float* __restrict__ a_src,
                            const float* __restrict__ a_dst,
                            float* __restrict__ ssrc,
                            float* __restrict__ sdst) {
    const int warp = threadIdx.x >> 5;
    const int lane = threadIdx.x & 31;
    const int row  = blockIdx.x * 8 + warp;
    if (row >= N_NODES) return;
    const float4* wr = (const float4*)(Wh + (size_t)row * D_FEAT);
    const float4* as = (const float4*)a_src;
    const float4* ad = (const float4*)a_dst;
    float s1 = 0.f, s2 = 0.f;
#pragma unroll
    for (int k = 0; k < 2; k++) {
        int idx = lane + 32 * k;
        float4 w = wr[idx];
        float4 u = as[idx];
        float4 v = ad[idx];
        s1 += w.x * u.x + w.y * u.y + w.z * u.z + w.w * u.w;
        s2 += w.x * v.x + w.y * v.y + w.z * v.z + w.w * v.w;
    }
#pragma unroll
    for (int o = 16; o > 0; o >>= 1) {
        s1 += __shfl_xor_sync(0xFFFFFFFFu, s1, o);
        s2 += __shfl_xor_sync(0xFFFFFFFFu, s2, o);
    }
    if (lane == 0) { ssrc[row] = s1; sdst[row] = s2; }
}

// ---------------- factors ----------------
__global__ void factor_kernel(const float* __restrict__ ssrc,
                              const float* __restrict__ sdst,
                              float* __restrict__ F1, float* __restrict__ F2,
                              float* __restrict__ G) {
    int j = blockIdx.x * 256 + threadIdx.x;
    float sd = sdst[j];
    float ss = ssrc[j];
    F1[j] = expf(sd);
    F2[j] = expf(ALPHA * sd);
    G[j]  = expf((ALPHA - 1.f) * ss);
}

// ---------------- fused aggregation (fp16 wmma, pipelined) ----------------
// 512 threads, 16 warps: warp w covers rows [ (w>>3)*32, +32 ), cols [ (w&7)*32, +32 )
// smem double buffered; adj register-prefetched 2 tiles ahead.

struct SmemLayout {
    half Whs[2][BN][WHS_LD];
    half Ps [2][BM][PS_LD];
    float Gs[BM];
    float THs[BM];
};

__global__ __launch_bounds__(512, 1)
void agg_kernel(const int* __restrict__ adj,
                const float* __restrict__ Wh,
                const float* __restrict__ ssrc,
                const float* __restrict__ sdst,
                const float* __restrict__ F1,
                const float* __restrict__ F2,
                const float* __restrict__ G,
                float* __restrict__ accU,
                float* __restrict__ Lout) {
    extern __shared__ char smem_raw[];
    SmemLayout* S = (SmemLayout*)smem_raw;

    const int i0   = blockIdx.x * BM;
    const int tid  = threadIdx.x;
    const int warp = tid >> 5;
    const int rg   = warp >> 3;   // 0..1 : 32-row group
    const int cg   = warp & 7;    // 0..7 : 32-col group

    const int pr = tid >> 3;      // 0..63 : P row
    const int pq = tid & 7;       // 0..7  : 8-col group

    if (tid < BM) {
        S->Gs[tid]  = G[i0 + tid];
        S->THs[tid] = -ssrc[i0 + tid];
    }

    wmma::fragment<wmma::accumulator, 16, 16, 16, float> acc[2][2];
#pragma unroll
    for (int a = 0; a < 2; a++)
#pragma unroll
        for (int b = 0; b < 2; b++) wmma::fill_fragment(acc[a][b], 0.f);

    float Lacc = 0.f;
    const float4* wv = (const float4*)Wh;

    // ---- helpers as macros (keep everything in registers) ----
#define ADJ_LOAD(t, A0, A1) {                                              \
        const int* arow = adj + (size_t)(i0 + pr) * N_NODES + (t) * BN + pq * 8; \
        A0 = *(const int4*)(arow);                                         \
        A1 = *(const int4*)(arow + 4);                                     \
    }

#define WH_LOAD_STORE(t, buf) {                                            \
        const float4* src = wv + (size_t)((t) * BN) * (D_FEAT / 4);        \
        _Pragma("unroll")                                                  \
        for (int i = tid; i < BN * (D_FEAT / 4); i += 512) {               \
            int r = i >> 6, c = i & 63;                                    \
            float4 v = src[(size_t)r * (D_FEAT / 4) + c];                  \
            half2* dst = (half2*)&S->Whs[buf][r][c * 4];                   \
            dst[0] = __floats2half2_rn(v.x, v.y);                          \
            dst[1] = __floats2half2_rn(v.z, v.w);                          \
        }                                                                  \
    }

#define BUILD_P(t, buf, A0, A1) {                                          \
        const int jc = (t) * BN + pq * 8;                                  \
        const float gi = S->Gs[pr], th = S->THs[pr];                       \
        float4 f1a = __ldg((const float4*)(F1 + jc));                      \
        float4 f1b = __ldg((const float4*)(F1 + jc + 4));                  \
        float4 f2a = __ldg((const float4*)(F2 + jc));                      \
        float4 f2b = __ldg((const float4*)(F2 + jc + 4));                  \
        float4 sda = __ldg((const float4*)(sdst + jc));                    \
        float4 sdb = __ldg((const float4*)(sdst + jc + 4));                \
        float p0 = A0.x ? (sda.x > th ? f1a.x : gi * f2a.x) : 0.f;         \
        float p1 = A0.y ? (sda.y > th ? f1a.y : gi * f2a.y) : 0.f;         \
        float p2 = A0.z ? (sda.z > th ? f1a.z : gi * f2a.z) : 0.f;         \
        float p3 = A0.w ? (sda.w > th ? f1a.w : gi * f2a.w) : 0.f;         \
        float p4 = A1.x ? (sdb.x > th ? f1b.x : gi * f2b.x) : 0.f;         \
        float p5 = A1.y ? (sdb.y > th ? f1b.y : gi * f2b.y) : 0.f;         \
        float p6 = A1.z ? (sdb.z > th ? f1b.z : gi * f2b.z) : 0.f;         \
        float p7 = A1.w ? (sdb.w > th ? f1b.w : gi * f2b.w) : 0.f;         \
        half2 h0 = __floats2half2_rn(p0, p1);                              \
        half2 h1 = __floats2half2_rn(p2, p3);                              \
        half2 h2 = __floats2half2_rn(p4, p5);                              \
        half2 h3 = __floats2half2_rn(p6, p7);                              \
        half2* pp = (half2*)&S->Ps[buf][pr][pq * 8];                       \
        pp[0] = h0; pp[1] = h1; pp[2] = h2; pp[3] = h3;                    \
        float2 l0 = __half22float2(h0), l1 = __half22float2(h1);           \
        float2 l2 = __half22float2(h2), l3 = __half22float2(h3);           \
        Lacc += (l0.x + l0.y) + (l1.x + l1.y) + (l2.x + l2.y) + (l3.x + l3.y); \
    }

#define MMA_STEP(buf) {                                                    \
        _Pragma("unroll")                                                  \
        for (int kk = 0; kk < BN; kk += 16) {                              \
            wmma::fragment<wmma::matrix_a, 16, 16, 16, half, wmma::row_major> af[2]; \
            wmma::fragment<wmma::matrix_b, 16, 16, 16, half, wmma::row_major> bf[2]; \
            af[0].x[0] = af[0].x[0];                                       \
            wmma::load_matrix_sync(af[0], &S->Ps[buf][rg * 32][kk], PS_LD);      \
            wmma::load_matrix_sync(af[1], &S->Ps[buf][rg * 32 + 16][kk], PS_LD); \
            wmma::load_matrix_sync(bf[0], &S->Whs[buf][kk][cg * 32], WHS_LD);    \
            wmma::load_matrix_sync(bf[1], &S->Whs[buf][kk][cg * 32 + 16], WHS_LD); \
            wmma::mma_sync(acc[0][0], af[0], bf[0], acc[0][0]);            \
            wmma::mma_sync(acc[0][1], af[0], bf[1], acc[0][1]);            \
            wmma::mma_sync(acc[1][0], af[1], bf[0], acc[1][0]);            \
            wmma::mma_sync(acc[1][1], af[1], bf[1], acc[1][1]);            \
        }                                                                  \
    }

    // ---- prologue: tile 0 resident, adj(1) in flight ----
    int4 a_pre0, a_pre1;
    ADJ_LOAD(0, a_pre0, a_pre1);
    WH_LOAD_STORE(0, 0);
    __syncthreads();                 // Gs/THs ready before BUILD_P reads them
    BUILD_P(0, 0, a_pre0, a_pre1);
    ADJ_LOAD(1, a_pre0, a_pre1);
    __syncthreads();

    // ---- main pipeline: one barrier per tile ----
    for (int t = 0; t < NT; t++) {
        const int cur = t & 1, nxt = cur ^ 1;
        if (t + 1 < NT) {
            BUILD_P(t + 1, nxt, a_pre0, a_pre1);
            if (t + 2 < NT) ADJ_LOAD(t + 2, a_pre0, a_pre1);
            WH_LOAD_STORE(t + 1, nxt);
        }
        MMA_STEP(cur);
        __syncthreads();
    }

    // ---- row sums over the 8 pq threads (consecutive lanes) ----
    Lacc += __shfl_xor_sync(0xFFFFFFFFu, Lacc, 1);
    Lacc += __shfl_xor_sync(0xFFFFFFFFu, Lacc, 2);
    Lacc += __shfl_xor_sync(0xFFFFFFFFu, Lacc, 4);
    if (pq == 0) Lout[i0 + pr] = Lacc;

    // ---- store unnormalized accumulators ----
#pragma unroll
    for (int a = 0; a < 2; a++)
#pragma unroll
        for (int b = 0; b < 2; b++)
            wmma::store_matrix_sync(accU + (size_t)(i0 + rg * 32 + a * 16) * D_FEAT
                                         + cg * 32 + b * 16,
                                    acc[a][b], D_FEAT, wmma::mem_row_major);
}

// ---------------- normalize: out = relu(accU) / L ----------------
__global__ void norm_kernel(float* __restrict__ buf, const float* __restrict__ L) {
    int idx = blockIdx.x * 256 + threadIdx.x;
    int row = idx >> 6;
    float inv = 1.0f / __ldg(&L[row]);
    float4 v = ((float4*)buf)[idx];
    v.x = fmaxf(v.x, 0.f) * inv;
    v.y = fmaxf(v.y, 0.f) * inv;
    v.z = fmaxf(v.z, 0.f) * inv;
    v.w = fmaxf(v.w, 0.f) * inv;
    ((float4*)buf)[idx] = v;
}

// ---------------- launch ----------------
extern "C" void kernel_launch(void* const* d_in, const int* in_sizes, int n_in,
                              void* d_out, int out_size) {
    const float* x     = (const float*)d_in[0];
    const int*   adj   = (const int*)  d_in[1];
    const float* W1    = (const float*)d_in[2];
    const float* a1src = (const float*)d_in[3];
    const float* a1dst = (const float*)d_in[4];
    const float* W2    = (const float*)d_in[5];
    const float* a2src = (const float*)d_in[6];
    const float* a2dst = (const float*)d_in[7];
    float* out = (float*)d_out;

    float *Wh, *h1, *ss, *sd, *F1, *F2, *G, *L;
    cudaGetSymbolAddress((void**)&Wh, g_Wh);
    cudaGetSymbolAddress((void**)&h1, g_h);
    cudaGetSymbolAddress((void**)&ss, g_ssrc);
    cudaGetSymbolAddress((void**)&sd, g_sdst);
    cudaGetSymbolAddress((void**)&F1, g_F1);
    cudaGetSymbolAddress((void**)&F2, g_F2);
    cudaGetSymbolAddress((void**)&G,  g_G);
    cudaGetSymbolAddress((void**)&L,  g_L);

    const int smem_bytes = (int)sizeof(SmemLayout);
    cudaFuncSetAttribute(agg_kernel, cudaFuncAttributeMaxDynamicSharedMemorySize, smem_bytes);

    dim3 ggrid(D_FEAT / 64, N_NODES / 64);
    const int nrm_blocks = (N_NODES * D_FEAT / 4) / 256;

    // ---- layer 1 ----
    gemm_kernel<<<ggrid, 256>>>(x, W1, Wh);
    proj_kernel<<<N_NODES / 8, 256>>>(Wh, a1src, a1dst, ss, sd);
    factor_kernel<<<N_NODES / 256, 256>>>(ss, sd, F1, F2, G);
    agg_kernel<<<N_NODES / BM, 512, smem_bytes>>>(adj, Wh, ss, sd, F1, F2, G, h1, L);
    norm_kernel<<<nrm_blocks, 256>>>(h1, L);

    // ---- layer 2 ----
    gemm_kernel<<<ggrid, 256>>>(h1, W2, Wh);
    proj_kernel<<<N_NODES / 8, 256>>>(Wh, a2src, a2dst, ss, sd);
    factor_kernel<<<N_NODES / 256, 256>>>(ss, sd, F1, F2, G);
    agg_kernel<<<N_NODES / BM, 512, smem_bytes>>>(adj, Wh, ss, sd, F1, F2, G, out, L);
    norm_kernel<<<nrm_blocks, 256>>>(out, L);
}